// round 17
// baseline (speedup 1.0000x reference)
#include <cuda_runtime.h>
#include <cuda_fp16.h>
#include <math.h>
#include <stdint.h>

#define D_MODEL 1024
#define D_INNER 2048
#define D_STATE 16
#define DT_RANK 64
#define CONV_K  4
#define BSZ     2
#define SEQ     2048
#define BL      (BSZ*SEQ)             // 4096
#define XDBL_C  (DT_RANK + 2*D_STATE) // 96
#define XPROJ_SPLITK 8

// ---------------- scratch (static device globals) ---------------------------
__device__ __align__(16) __half g_xn_hi[BL * D_MODEL];
__device__ __align__(16) __half g_xz_h [BL * 2 * D_INNER];
__device__ __align__(16) __half g_u_hi [BL * D_INNER];
__device__ __align__(16) float  g_xdbl [BL * XDBL_C];
__device__ __align__(16) __half g_xd_hi[BL * XDBL_C];
__device__ __align__(16) float  g_part [XPROJ_SPLITK * BL * XDBL_C];
__device__ __align__(16) __half g_dl   [BL * D_INNER];
__device__ __align__(16) __half g_y_hi [BL * D_INNER];
__device__ __align__(16) __half g_wi_hi[2 * D_INNER * D_MODEL];
__device__ __align__(16) __half g_xp_hi[XDBL_C * D_INNER];
__device__ __align__(16) __half g_dw_hi[D_INNER * DT_RANK];
__device__ __align__(16) __half g_wo_hi[D_MODEL * D_INNER];

// ---------------- helpers ----------------------------------------------------
__device__ __forceinline__ void cp16(void* dst_smem, const void* src, int sz) {
    uint32_t d = (uint32_t)__cvta_generic_to_shared(dst_smem);
    asm volatile("cp.async.cg.shared.global [%0], [%1], 16, %2;\n"
                 :: "r"(d), "l"(src), "r"(sz));
}
__device__ __forceinline__ void cp_commit() {
    asm volatile("cp.async.commit_group;\n");
}
template<int N_> __device__ __forceinline__ void cp_wait() {
    asm volatile("cp.async.wait_group %0;\n" :: "n"(N_));
}
__device__ __forceinline__ uint2 h_pack4(float4 v) {
    __half2 a = __halves2half2(__float2half_rn(v.x), __float2half_rn(v.y));
    __half2 b = __halves2half2(__float2half_rn(v.z), __float2half_rn(v.w));
    uint2 r; r.x = *(uint32_t*)&a; r.y = *(uint32_t*)&b;
    return r;
}
__device__ __forceinline__ float4 h_unpack4(uint2 h) {
    __half2 a = *(__half2*)&h.x, b = *(__half2*)&h.y;
    return make_float4(__low2float(a), __high2float(a),
                       __low2float(b), __high2float(b));
}
__device__ __forceinline__ void mma16(float* c, const uint32_t* a, const uint32_t* b) {
    asm volatile(
        "mma.sync.aligned.m16n8k16.row.col.f32.f16.f16.f32 "
        "{%0,%1,%2,%3}, {%4,%5,%6,%7}, {%8,%9}, {%0,%1,%2,%3};\n"
        : "+f"(c[0]), "+f"(c[1]), "+f"(c[2]), "+f"(c[3])
        : "r"(a[0]), "r"(a[1]), "r"(a[2]), "r"(a[3]), "r"(b[0]), "r"(b[1]));
}
#define LDSM_X4(r0, r1, r2, r3, addr)                                       \
    asm volatile("ldmatrix.sync.aligned.m8n8.x4.shared.b16 "                \
                 "{%0,%1,%2,%3}, [%4];"                                     \
                 : "=r"(r0), "=r"(r1), "=r"(r2), "=r"(r3) : "r"(addr))

// K-chunk 64: rows of 64 halfs padded to 72 (conflict-free ldmatrix)
#define RS_H    72
#define TILE_A_H (128 * RS_H)             // 9216 halfs

// ================= single-pass fp16 GEMM, K-chunk 64, 3-stage ===============
// CTA tile 128 x BN (BN=128: 2 CTA/SM; BN=256: 1 CTA/SM). 8 warps 2x4,
// warp tile 64 x (BN/4).
// EPI: 0 fp32 out | 1 softplus(acc+bias[n]) -> half | 2 fp32 + res | 3 half out
template<int BN> struct GCfg {
    static const int TILE_B_H = BN * RS_H;
    static const int STAGE_H  = TILE_A_H + TILE_B_H;
    static const int SMEM     = 3 * STAGE_H * 2;
    static const int NI       = BN / 32;          // mma n-tiles per warp
    static const int OCC      = (BN == 128) ? 2 : 1;
};

template<int BN, int EPI, int SPLITK>
__global__ __launch_bounds__(256, GCfg<BN>::OCC) void gemm_1p(
    const __half* __restrict__ Ahi, int lda,
    const __half* __restrict__ Bhi, int ldb,
    void* __restrict__ Cout, int ldc, int M, int N, int K,
    const float* __restrict__ bias, const float* __restrict__ res)
{
    constexpr int NI = GCfg<BN>::NI;
    constexpr int STAGE_H = GCfg<BN>::STAGE_H;
    extern __shared__ __half sm[];
    int tid = threadIdx.x;
    int m0 = blockIdx.y * 128;
    int n0 = blockIdx.x * BN;

    float* Cf = (float*)Cout;
    __half* Ch = (__half*)Cout;

    if (SPLITK > 1) {
        int z = blockIdx.z;
        int Ks = K / SPLITK;
        Ahi += (size_t)z * Ks;
        Bhi += (size_t)z * Ks;
        Cf += (size_t)z * M * ldc;
        K = Ks;
    }
    int KT = K / 64;

    int lane = tid & 31, wid = tid >> 5;
    int p = lane >> 2, q = lane & 3;
    int wm = (wid & 1) * 64;
    int wn = (wid >> 1) * (BN / 4);

    float acc[4][NI][4];
    #pragma unroll
    for (int i = 0; i < 4; i++)
        #pragma unroll
        for (int j = 0; j < NI; j++)
            #pragma unroll
            for (int r = 0; r < 4; r++) acc[i][j][r] = 0.f;

    auto load_stage = [&](int kt, int slot) {
        __half* base = sm + slot * STAGE_H;
        int k0 = kt * 64;
        constexpr int TOT = (128 + BN) * 8;
        #pragma unroll
        for (int c = tid; c < TOT; c += 256) {
            if (c < 1024) {
                int r = c >> 3, j = c & 7;
                cp16(base + r * RS_H + j * 8,
                     Ahi + (size_t)(m0 + r) * lda + k0 + j * 8, 16);
            } else {
                int idx = c - 1024;
                int r = idx >> 3, j = idx & 7;
                int n = n0 + r;
                int sz = (n < N) ? 16 : 0;
                int rr = sz ? n : 0;
                cp16(base + TILE_A_H + r * RS_H + j * 8,
                     Bhi + (size_t)rr * ldb + k0 + j * 8, sz);
            }
        }
    };

    load_stage(0, 0); cp_commit();
    if (KT > 1) load_stage(1, 1);
    cp_commit();

    uint32_t smbase = (uint32_t)__cvta_generic_to_shared(sm);
    uint32_t a_off = ((wm + (lane & 15)) * RS_H + (lane >> 4) * 8) * 2;
    uint32_t b_off = ((wn + (lane >> 4) * 8 + (lane & 7)) * RS_H
                      + ((lane >> 3) & 1) * 8) * 2;

    for (int kt = 0; kt < KT; kt++) {
        cp_wait<1>();
        __syncthreads();
        if (kt + 2 < KT) load_stage(kt + 2, (kt + 2) % 3);
        cp_commit();

        uint32_t st = smbase + (kt % 3) * STAGE_H * 2;
        uint32_t aHi = st + a_off;
        uint32_t bHi = st + TILE_A_H * 2 + b_off;

        #pragma unroll
        for (int s = 0; s < 4; s++) {
            uint32_t ko = s * 32;
            uint32_t bh[NI][2];
            #pragma unroll
            for (int nb = 0; nb < NI / 2; nb++)
                LDSM_X4(bh[2*nb][0], bh[2*nb][1], bh[2*nb+1][0], bh[2*nb+1][1],
                        bHi + nb * 16 * RS_H * 2 + ko);
            #pragma unroll
            for (int mi = 0; mi < 4; mi++) {
                uint32_t ah[4];
                LDSM_X4(ah[0], ah[1], ah[2], ah[3], aHi + mi * 16 * RS_H * 2 + ko);
                #pragma unroll
                for (int ni = 0; ni < NI; ni++)
                    mma16(acc[mi][ni], ah, bh[ni]);
            }
        }
    }

    #pragma unroll
    for (int mi = 0; mi < 4; mi++) {
        int row = m0 + wm + mi * 16 + p;
        #pragma unroll
        for (int ni = 0; ni < NI; ni++) {
            int col = n0 + wn + ni * 8 + q * 2;
            if (col < N) {
                float v[4] = { acc[mi][ni][0], acc[mi][ni][1],
                               acc[mi][ni][2], acc[mi][ni][3] };
                if (EPI == 1) {
                    #pragma unroll
                    for (int r = 0; r < 4; r++) {
                        float t = v[r] + bias[col + (r & 1)];
                        float e = __expf(t);
                        v[r] = (t > 15.f) ? t : log1pf(e);
                    }
                }
                if (EPI == 1 || EPI == 3) {
                    __half2 v01 = __halves2half2(__float2half_rn(v[0]),
                                                 __float2half_rn(v[1]));
                    __half2 v23 = __halves2half2(__float2half_rn(v[2]),
                                                 __float2half_rn(v[3]));
                    *(__half2*)(Ch + (size_t)row * ldc + col) = v01;
                    *(__half2*)(Ch + (size_t)(row + 8) * ldc + col) = v23;
                } else {
                    if (EPI == 2) {
                        v[0] += res[(size_t)row * ldc + col];
                        v[1] += res[(size_t)row * ldc + col + 1];
                        v[2] += res[(size_t)(row + 8) * ldc + col];
                        v[3] += res[(size_t)(row + 8) * ldc + col + 1];
                    }
                    float* c0 = Cf + (size_t)row * ldc + col;
                    float* c1 = Cf + (size_t)(row + 8) * ldc + col;
                    c0[0] = v[0]; c0[1] = v[1];
                    c1[0] = v[2]; c1[1] = v[3];
                }
            }
        }
    }
}

// ---------------- fused weight splits (all 4 in one launch) -------------------
#define N_WI  (2 * D_INNER * D_MODEL)
#define N_WO  (D_MODEL * D_INNER)
#define N_XP  (XDBL_C * D_INNER)
#define N_DW  (D_INNER * DT_RANK)
#define N_SPLIT_TOT (N_WI + N_WO + N_XP + N_DW)

__global__ __launch_bounds__(256) void split_all_kernel(
    const float* __restrict__ wi, const float* __restrict__ wo,
    const float* __restrict__ xp, const float* __restrict__ dw,
    __half* __restrict__ wi_h, __half* __restrict__ wo_h,
    __half* __restrict__ xp_h, __half* __restrict__ dw_h)
{
    int i = (blockIdx.x * 256 + threadIdx.x) * 8;
    if (i >= N_SPLIT_TOT) return;
    const float* src; __half* dst; int off;
    if (i < N_WI)                    { src = wi; dst = wi_h; off = i; }
    else if (i < N_WI + N_WO)        { src = wo; dst = wo_h; off = i - N_WI; }
    else if (i < N_WI + N_WO + N_XP) { src = xp; dst = xp_h; off = i - N_WI - N_WO; }
    else                             { src = dw; dst = dw_h; off = i - N_WI - N_WO - N_XP; }
    float4 a = *(const float4*)(src + off);
    float4 b = *(const float4*)(src + off + 4);
    uint2 h0 = h_pack4(a), h1 = h_pack4(b);
    *(uint4*)(dst + off) = make_uint4(h0.x, h0.y, h1.x, h1.y);
}

// ---------------- LayerNorm (hi only) -----------------------------------------
__global__ __launch_bounds__(256) void ln_kernel(
    const float* __restrict__ x, const float* __restrict__ g,
    const float* __restrict__ b, __half* __restrict__ ohi)
{
    int row = blockIdx.x;
    const float4* xr = (const float4*)(x + (size_t)row * D_MODEL);
    float4 v = xr[threadIdx.x];
    float s  = v.x + v.y + v.z + v.w;
    float ss = v.x*v.x + v.y*v.y + v.z*v.z + v.w*v.w;
    #pragma unroll
    for (int o = 16; o; o >>= 1) {
        s  += __shfl_xor_sync(0xffffffffu, s, o);
        ss += __shfl_xor_sync(0xffffffffu, ss, o);
    }
    __shared__ float red[16];
    __shared__ float mu_s, rstd_s;
    int w = threadIdx.x >> 5, lane = threadIdx.x & 31;
    if (lane == 0) { red[w] = s; red[8 + w] = ss; }
    __syncthreads();
    if (threadIdx.x == 0) {
        float S = 0.f, SS = 0.f;
        #pragma unroll
        for (int i = 0; i < 8; i++) { S += red[i]; SS += red[8 + i]; }
        float mu = S * (1.f / D_MODEL);
        float var = SS * (1.f / D_MODEL) - mu * mu;
        mu_s = mu; rstd_s = rsqrtf(var + 1e-5f);
    }
    __syncthreads();
    float mu = mu_s, r = rstd_s;
    float4 gv = ((const float4*)g)[threadIdx.x];
    float4 bv = ((const float4*)b)[threadIdx.x];
    float4 o;
    o.x = (v.x - mu) * r * gv.x + bv.x;
    o.y = (v.y - mu) * r * gv.y + bv.y;
    o.z = (v.z - mu) * r * gv.z + bv.z;
    o.w = (v.w - mu) * r * gv.w + bv.w;
    ((uint2*)(ohi + (size_t)row * D_MODEL))[threadIdx.x] = h_pack4(o);
}

// ---------------- split-K reduce for x_proj (fp32 + hi) -----------------------
__global__ __launch_bounds__(256) void xproj_reduce(
    const float* __restrict__ part, float* __restrict__ out,
    __half* __restrict__ ohi)
{
    int i = (blockIdx.x * 256 + threadIdx.x) * 4;
    if (i >= BL * XDBL_C) return;
    const int stride = BL * XDBL_C;
    float4 s = *(const float4*)(part + i);
    #pragma unroll
    for (int z = 1; z < XPROJ_SPLITK; z++) {
        float4 p = *(const float4*)(part + z * stride + i);
        s.x += p.x; s.y += p.y; s.z += p.z; s.w += p.w;
    }
    *(float4*)(out + i) = s;
    *(uint2*)(ohi + i) = h_pack4(s);
}

// ---------------- causal depthwise conv (K=4) + SiLU, time-tiled x4 ----------
__global__ __launch_bounds__(256) void conv_silu_kernel(
    const __half* __restrict__ xz, const float* __restrict__ w,
    const float* __restrict__ bias, __half* __restrict__ uhi)
{
    const int ND4 = D_INNER / 4;
    const int NT4 = SEQ / 4;
    int idx = blockIdx.x * 256 + threadIdx.x;
    if (idx >= BSZ * NT4 * ND4) return;
    int d4 = (idx % ND4) * 4;
    int t0 = ((idx / ND4) % NT4) * 4;
    int b  = idx / (ND4 * NT4);

    float4 bi = *(const float4*)(bias + d4);
    float4 wr[4];
    #pragma unroll
    for (int c = 0; c < 4; c++) wr[c] = *(const float4*)(w + (d4 + c) * CONV_K);

    float4 xv[7];
    #pragma unroll
    for (int j = 0; j < 7; j++) {
        int ts = t0 - 3 + j;
        if (ts >= 0) {
            uint2 xh = *(const uint2*)(xz + (size_t)(b * SEQ + ts) * (2 * D_INNER) + d4);
            xv[j] = h_unpack4(xh);
        } else {
            xv[j] = make_float4(0.f, 0.f, 0.f, 0.f);
        }
    }

    #pragma unroll
    for (int o = 0; o < 4; o++) {
        float4 acc = bi;
        #pragma unroll
        for (int k = 0; k < CONV_K; k++) {
            float4 xk = xv[o + k];
            acc.x += ((const float*)&wr[0])[k] * xk.x;
            acc.y += ((const float*)&wr[1])[k] * xk.y;
            acc.z += ((const float*)&wr[2])[k] * xk.z;
            acc.w += ((const float*)&wr[3])[k] * xk.w;
        }
        float4 val;
        val.x = acc.x / (1.f + __expf(-acc.x));
        val.y = acc.y / (1.f + __expf(-acc.y));
        val.z = acc.z / (1.f + __expf(-acc.z));
        val.w = acc.w / (1.f + __expf(-acc.w));
        size_t oi = (size_t)(b * SEQ + t0 + o) * D_INNER + d4;
        *(uint2*)(uhi + oi) = h_pack4(val);
    }
}

// ---------------- selective scan: 8 lanes/channel, 2 states/lane --------------
#define SC_DC 16
#define SC_TC 64
__global__ __launch_bounds__(128) void scan_kernel(
    const __half* __restrict__ uhi, const __half* __restrict__ dl,
    const float* __restrict__ xdbl, const float* __restrict__ A_log,
    const __half* __restrict__ xz, const float* __restrict__ Dp,
    __half* __restrict__ yhi)
{
    __shared__ float u_s [SC_TC][SC_DC];
    __shared__ float du_s[SC_TC][SC_DC];
    __shared__ float dl_s[SC_TC][SC_DC];
    __shared__ float B_s [SC_TC][D_STATE];
    __shared__ float C_s [SC_TC][D_STATE];
    __shared__ float y_s [SC_TC][SC_DC];

    int b  = blockIdx.y;
    int d0 = blockIdx.x * SC_DC;
    int tid = threadIdx.x;
    int g = tid >> 3;
    int n = tid & 7;
    int d = d0 + g;

    float a0 = -expf(A_log[d * D_STATE + n]);
    float a1 = -expf(A_log[d * D_STATE + n + 8]);
    float s0 = 0.f, s1 = 0.f;

    for (int t0 = 0; t0 < SEQ; t0 += SC_TC) {
        {
            int i = tid * 8;
            int tt = i >> 4, gg = i & 15;
            size_t gi = (size_t)(b * SEQ + t0 + tt) * D_INNER + d0 + gg;
            uint4 uh = *(const uint4*)(uhi + gi);
            uint4 dh = *(const uint4*)(dl + gi);
            float4 u0 = h_unpack4(make_uint2(uh.x, uh.y));
            float4 u1 = h_unpack4(make_uint2(uh.z, uh.w));
            float4 d0f = h_unpack4(make_uint2(dh.x, dh.y));
            float4 d1f = h_unpack4(make_uint2(dh.z, dh.w));
            *(float4*)&u_s [tt][gg]     = u0;
            *(float4*)&u_s [tt][gg + 4] = u1;
            *(float4*)&dl_s[tt][gg]     = d0f;
            *(float4*)&dl_s[tt][gg + 4] = d1f;
            *(float4*)&du_s[tt][gg]     = make_float4(d0f.x*u0.x, d0f.y*u0.y, d0f.z*u0.z, d0f.w*u0.w);
            *(float4*)&du_s[tt][gg + 4] = make_float4(d1f.x*u1.x, d1f.y*u1.y, d1f.z*u1.z, d1f.w*u1.w);
        }
        for (int i = tid * 4; i < SC_TC * 32; i += 512) {
            int tt = i >> 5, pos = i & 31;
            const float* r = xdbl + (size_t)(b * SEQ + t0 + tt) * XDBL_C + DT_RANK;
            float4 v = *(const float4*)(r + pos);
            if (pos < 16) *(float4*)&B_s[tt][pos] = v;
            else          *(float4*)&C_s[tt][pos - 16] = v;
        }
        __syncthreads();
        #pragma unroll 4
        for (int t = 0; t < SC_TC; t++) {
            float dlt = dl_s[t][g];
            float du  = du_s[t][g];
            float dA0 = __expf(dlt * a0);
            float dA1 = __expf(dlt * a1);
            s0 = fmaf(dA0, s0, du * B_s[t][n]);
            s1 = fmaf(dA1, s1, du * B_s[t][n + 8]);
            float part = fmaf(s1, C_s[t][n + 8], s0 * C_s[t][n]);
            part += __shfl_xor_sync(0xffffffffu, part, 4);
            part += __shfl_xor_sync(0xffffffffu, part, 2);
            part += __shfl_xor_sync(0xffffffffu, part, 1);
            if (n == 0) y_s[t][g] = part;
        }
        __syncthreads();
        {
            int i = tid * 8;
            int tt = i >> 4, gg = i & 15;
            int rowg = b * SEQ + t0 + tt;
            uint4 zh = *(const uint4*)(xz + (size_t)rowg * (2 * D_INNER) + D_INNER + d0 + gg);
            float4 z0 = h_unpack4(make_uint2(zh.x, zh.y));
            float4 z1 = h_unpack4(make_uint2(zh.z, zh.w));
            float4 u0 = *(const float4*)&u_s[tt][gg];
            float4 u1 = *(const float4*)&u_s[tt][gg + 4];
            float4 y0 = *(const float4*)&y_s[tt][gg];
            float4 y1 = *(const float4*)&y_s[tt][gg + 4];
            float4 p0 = *(const float4*)(Dp + d0 + gg);
            float4 p1 = *(const float4*)(Dp + d0 + gg + 4);
            float4 v0, v1;
            v0.x = (y0.x + u0.x * p0.x) * (z0.x / (1.f + __expf(-z0.x)));
            v0.y = (y0.y + u0.y * p0.y) * (z0.y / (1.f + __expf(-z0.y)));
            v0.z = (y0.z + u0.z * p0.z) * (z0.z / (1.f + __expf(-z0.z)));
            v0.w = (y0.w + u0.w * p0.w) * (z0.w / (1.f + __expf(-z0.w)));
            v1.x = (y1.x + u1.x * p1.x) * (z1.x / (1.f + __expf(-z1.x)));
            v1.y = (y1.y + u1.y * p1.y) * (z1.y / (1.f + __expf(-z1.y)));
            v1.z = (y1.z + u1.z * p1.z) * (z1.z / (1.f + __expf(-z1.z)));
            v1.w = (y1.w + u1.w * p1.w) * (z1.w / (1.f + __expf(-z1.w)));
            uint2 h0 = h_pack4(v0), h1 = h_pack4(v1);
            size_t oi = (size_t)rowg * D_INNER + d0 + gg;
            *(uint4*)(yhi + oi) = make_uint4(h0.x, h0.y, h1.x, h1.y);
        }
        __syncthreads();
    }
}

// ---------------- launch ------------------------------------------------------
extern "C" void kernel_launch(void* const* d_in, const int* in_sizes, int n_in,
                              void* d_out, int out_size)
{
    const float* x      = (const float*)d_in[0];
    const float* ln_g   = (const float*)d_in[1];
    const float* ln_b   = (const float*)d_in[2];
    const float* W_in   = (const float*)d_in[3];
    const float* conv_w = (const float*)d_in[4];
    const float* conv_b = (const float*)d_in[5];
    const float* A_log  = (const float*)d_in[6];
    const float* D_prm  = (const float*)d_in[7];
    const float* x_proj = (const float*)d_in[8];
    const float* dt_w   = (const float*)d_in[9];
    const float* dt_b   = (const float*)d_in[10];
    const float* W_out  = (const float*)d_in[11];
    float* out = (float*)d_out;

    __half *xn_hi, *xz_h, *u_hi, *xd_hi, *dl, *y_hi;
    __half *wi_hi, *xp_hi, *dw_hi, *wo_hi;
    float *xdbl, *part;
    cudaGetSymbolAddress((void**)&xn_hi, g_xn_hi);
    cudaGetSymbolAddress((void**)&xz_h,  g_xz_h);
    cudaGetSymbolAddress((void**)&u_hi,  g_u_hi);
    cudaGetSymbolAddress((void**)&xdbl,  g_xdbl);
    cudaGetSymbolAddress((void**)&xd_hi, g_xd_hi);
    cudaGetSymbolAddress((void**)&part,  g_part);
    cudaGetSymbolAddress((void**)&dl,    g_dl);
    cudaGetSymbolAddress((void**)&y_hi,  g_y_hi);
    cudaGetSymbolAddress((void**)&wi_hi, g_wi_hi);
    cudaGetSymbolAddress((void**)&xp_hi, g_xp_hi);
    cudaGetSymbolAddress((void**)&dw_hi, g_dw_hi);
    cudaGetSymbolAddress((void**)&wo_hi, g_wo_hi);

    constexpr int SM256 = GCfg<256>::SMEM;   // 165888
    constexpr int SM128 = GCfg<128>::SMEM;   // 110592
    cudaFuncSetAttribute(gemm_1p<256,3,1>, cudaFuncAttributeMaxDynamicSharedMemorySize, SM256);
    cudaFuncSetAttribute(gemm_1p<128,0,XPROJ_SPLITK>, cudaFuncAttributeMaxDynamicSharedMemorySize, SM128);
    cudaFuncSetAttribute(gemm_1p<256,1,1>, cudaFuncAttributeMaxDynamicSharedMemorySize, SM256);
    cudaFuncSetAttribute(gemm_1p<256,2,1>, cudaFuncAttributeMaxDynamicSharedMemorySize, SM256);

    // 0. all weight splits in one launch
    split_all_kernel<<<(N_SPLIT_TOT/8 + 255)/256, 256>>>(
        W_in, W_out, x_proj, dt_w, wi_hi, wo_hi, xp_hi, dw_hi);

    // 1. LayerNorm -> xn hi
    ln_kernel<<<BL, 256>>>(x, ln_g, ln_b, xn_hi);

    // 2. xz = xn @ W_in^T -> fp16  (4096 x 4096 x 1024)
    gemm_1p<256,3,1><<<dim3(2*D_INNER/256, BL/128), 256, SM256>>>(
        xn_hi, D_MODEL, wi_hi, D_MODEL,
        xz_h, 2*D_INNER, BL, 2*D_INNER, D_MODEL, nullptr, nullptr);

    // 3. causal depthwise conv + SiLU -> u hi (time-tiled x4)
    conv_silu_kernel<<<(BL*D_INNER/16 + 255)/256, 256>>>(xz_h, conv_w, conv_b, u_hi);

    // 4. x_dbl = u @ x_proj^T  (4096 x 96 x 2048), split-K=8
    gemm_1p<128,0,XPROJ_SPLITK><<<dim3(1, BL/128, XPROJ_SPLITK), 256, SM128>>>(
        u_hi, D_INNER, xp_hi, D_INNER,
        part, XDBL_C, BL, XDBL_C, D_INNER, nullptr, nullptr);
    xproj_reduce<<<(BL*XDBL_C/4 + 255)/256, 256>>>(part, xdbl, xd_hi);

    // 5. delta = softplus(dt_r @ dt_w^T + dt_b) -> fp16  (4096 x 2048 x 64)
    gemm_1p<256,1,1><<<dim3(D_INNER/256, BL/128), 256, SM256>>>(
        xd_hi, XDBL_C, dw_hi, DT_RANK,
        dl, D_INNER, BL, D_INNER, DT_RANK, dt_b, nullptr);

    // 6. selective scan + fused gate -> y hi
    scan_kernel<<<dim3(D_INNER/SC_DC, BSZ), 128>>>(
        u_hi, dl, xdbl, A_log, xz_h, D_prm, y_hi);

    // 7. out = y @ W_out^T + x  (4096 x 1024 x 2048)
    gemm_1p<256,2,1><<<dim3(D_MODEL/256, BL/128), 256, SM256>>>(
        y_hi, D_INNER, wo_hi, D_INNER,
        out, D_MODEL, BL, D_MODEL, D_INNER, nullptr, x);
}